// round 14
// baseline (speedup 1.0000x reference)
#include <cuda_runtime.h>
#include <cuda_fp16.h>

#define NLAT_IN  181
#define NLON_IN  360
#define NLAT_OUT 361
#define NLON_OUT 720
#define KSIZE    3
#define CIN      16
#define COUT     16
#define NNZ      8192
#define NBIN     (NLAT_OUT * 2)   // (hi, parity)
#define MAXB     128
#define NEIN     (NLAT_IN * KSIZE)  // 543 einsum blocks
#define NBINB    64                 // binning blocks (128 entries each)
#define NROW     (KSIZE * NLAT_IN)  // 543 xw rows
#define NUNIT    (NBIN * 2)         // 1444 (bin, channel-half) work units
#define PGRID    592                // persistent k_main blocks (<=1 wave)

// xw: [row][h][w] as uint4 (8 fp16 channels packed). 6.25MB
__device__ uint4 d_xw4[NROW * 2 * NLON_IN];
// Two independent bucket copies (one per channel-half unit).
// Entry: {meta, val_bits, orig_idx, 0}; meta = (row4<<9)|s
__device__ int4 d_bk0[NBIN * MAXB];
__device__ int4 d_bk1[NBIN * MAXB];
__device__ int  d_cnt0[NBIN];   // statically zero; consuming unit resets its own
__device__ int  d_cnt1[NBIN];
__device__ int  d_ticket;       // reset by k_prep each launch

// ---------------------------------------------------------------------------
// Fused: blocks 0..542 = channel-mix einsum; blocks 543..606 = atomic binning.
__global__ void __launch_bounds__(768)
k_prep(const float* __restrict__ x, const float* __restrict__ wgt,
       const int* __restrict__ ker_idx, const int* __restrict__ row_idx,
       const int* __restrict__ col_idx, const float* __restrict__ vals) {
    int t = threadIdx.x;

    if (blockIdx.x >= NEIN) {
        // ---------------- binning path ----------------
        if (blockIdx.x == NEIN && t == 0) d_ticket = 0;  // replay-safe reset
        if (t >= 128) return;
        int i   = (blockIdx.x - NEIN) * 128 + t;
        int col = col_idx[i];
        int hi  = col / NLON_OUT;
        int p   = col - hi * NLON_OUT;
        int bin = hi * 2 + (p & 1);
        int row4 = (ker_idx[i] * NLAT_IN + row_idx[i]) * (2 * NLON_IN);
        int4 ent = make_int4((row4 << 9) | (p >> 1),
                             __float_as_int(vals[i]), i, 0);
        int s0 = atomicAdd(&d_cnt0[bin], 1);
        if (s0 < MAXB) d_bk0[bin * MAXB + s0] = ent;
        int s1 = atomicAdd(&d_cnt1[bin], 1);
        if (s1 < MAXB) d_bk1[bin * MAXB + s1] = ent;
        return;
    }

    // ---------------- einsum path ----------------
    __shared__ float sw[COUT * CIN];  // [o][c] for this k
    int b   = blockIdx.x;
    int tin = b % NLAT_IN;
    int k   = b / NLAT_IN;
    if (t < COUT * CIN) sw[t] = wgt[t * KSIZE + k];  // wgt[o][c][k]
    __syncthreads();

    int h = (t >= 384) ? 1 : 0;
    int w = t - h * 384;
    if (w >= NLON_IN) return;

    float acc[8];
#pragma unroll
    for (int o = 0; o < 8; o++) acc[o] = 0.f;

#pragma unroll
    for (int c = 0; c < CIN; c++) {
        float xc = x[(c * NLAT_IN + tin) * NLON_IN + w];
#pragma unroll
        for (int o = 0; o < 8; o++)
            acc[o] += xc * sw[(h * 8 + o) * CIN + c];
    }
    __half2 p0 = __floats2half2_rn(acc[0], acc[1]);
    __half2 p1 = __floats2half2_rn(acc[2], acc[3]);
    __half2 p2 = __floats2half2_rn(acc[4], acc[5]);
    __half2 p3 = __floats2half2_rn(acc[6], acc[7]);
    uint4 val;
    val.x = *(unsigned*)&p0;
    val.y = *(unsigned*)&p1;
    val.z = *(unsigned*)&p2;
    val.w = *(unsigned*)&p3;
    d_xw4[(k * NLAT_IN + tin) * (2 * NLON_IN) + h * NLON_IN + w] = val;
}

// ---------------------------------------------------------------------------
// Persistent main gather. PDL: launches during k_prep's drain, then waits.
// Each block pulls (bin, channel-half) units off a global ticket; per unit:
// stage private bucket, rank-sort by orig idx (determinism), gather with
// 1 x LDG.128 per entry (4 in flight), sentinel-padded (no tail loop).
__global__ void __launch_bounds__(384)
k_main(const float* __restrict__ bias, float* __restrict__ out) {
#if __CUDA_ARCH__ >= 900
    cudaGridDependencySynchronize();
#endif
    __shared__ int  sidx[MAXB];
    __shared__ int2 sraw[MAXB];
    __shared__ __align__(16) int2 se[MAXB];
    __shared__ int sunit;
    int tid = threadIdx.x;

    for (;;) {
        if (tid == 0) sunit = atomicAdd(&d_ticket, 1);
        __syncthreads();
        int u = sunit;
        if (u >= NUNIT) break;

        int b  = u >> 1;           // bin
        int h  = u & 1;            // channel half
        int hi = b >> 1;
        int q  = b & 1;

        int* cntp = h ? d_cnt1 : d_cnt0;
        const int4* bk = (h ? d_bk1 : d_bk0) + b * MAXB;

        int cnt = cntp[b];
        if (cnt > MAXB) cnt = MAXB;
        int cntP = (cnt + 3) & ~3;
        if (tid < cnt) {
            int4 e = bk[tid];
            sraw[tid] = make_int2(e.x, e.y);
            sidx[tid] = e.z;
        }
        __syncthreads();
        if (tid == 0) cntp[b] = 0;          // reset for next replay
        if (tid < cnt) {
            int my = sidx[tid];
            int r = 0;
            for (int j = 0; j < cnt; j++) r += (sidx[j] < my);
            se[r] = sraw[tid];
        }
        if (tid >= cnt && tid < cntP) se[tid] = make_int2(0, 0);  // sentinel
        __syncthreads();

        int jj = tid;
        if (jj < NLON_IN) {
            const uint4* __restrict__ xbase = d_xw4 + h * NLON_IN;
            float acc[8];
#pragma unroll
            for (int o = 0; o < 8; o++) acc[o] = 0.f;

            const int4* se4 = (const int4*)se;
            for (int e = 0; e < cntP; e += 4) {
                int4 A = se4[e >> 1];
                int4 B = se4[(e >> 1) + 1];
                int m0 = A.x, m1 = A.z, m2 = B.x, m3 = B.z;
                float v0 = __int_as_float(A.y), v1 = __int_as_float(A.w);
                float v2 = __int_as_float(B.y), v3 = __int_as_float(B.w);
                int w0 = jj - (m0 & 511); if (w0 < 0) w0 += NLON_IN;
                int w1 = jj - (m1 & 511); if (w1 < 0) w1 += NLON_IN;
                int w2 = jj - (m2 & 511); if (w2 < 0) w2 += NLON_IN;
                int w3 = jj - (m3 & 511); if (w3 < 0) w3 += NLON_IN;
                uint4 d0 = xbase[(m0 >> 9) + w0];
                uint4 d1 = xbase[(m1 >> 9) + w1];
                uint4 d2 = xbase[(m2 >> 9) + w2];
                uint4 d3 = xbase[(m3 >> 9) + w3];
#pragma unroll
                for (int j = 0; j < 4; j++) {
                    float2 f0 = __half22float2(*(const __half2*)(&d0.x + j));
                    float2 f1 = __half22float2(*(const __half2*)(&d1.x + j));
                    float2 f2 = __half22float2(*(const __half2*)(&d2.x + j));
                    float2 f3 = __half22float2(*(const __half2*)(&d3.x + j));
                    acc[2 * j]     += v0 * f0.x + v1 * f1.x + v2 * f2.x + v3 * f3.x;
                    acc[2 * j + 1] += v0 * f0.y + v1 * f1.y + v2 * f2.y + v3 * f3.y;
                }
            }

            int lon = q + 2 * jj;
            const int cs = NLAT_OUT * NLON_OUT;
            float* dst = out + (h * 8) * cs + hi * NLON_OUT + lon;
#pragma unroll
            for (int o = 0; o < 8; o++) dst[o * cs] = acc[o] + bias[h * 8 + o];
        }
        __syncthreads();   // protect smem before next unit's staging
    }
}

// ---------------------------------------------------------------------------
extern "C" void kernel_launch(void* const* d_in, const int* in_sizes, int n_in,
                              void* d_out, int out_size) {
    const float* x       = (const float*)d_in[0];
    const float* weight  = (const float*)d_in[1];
    const float* bias    = (const float*)d_in[2];
    const int*   ker_idx = (const int*)d_in[3];
    const int*   row_idx = (const int*)d_in[4];
    const int*   col_idx = (const int*)d_in[5];
    const float* vals    = (const float*)d_in[6];
    float* out = (float*)d_out;

    (void)in_sizes; (void)n_in; (void)out_size;

    k_prep<<<NEIN + NBINB, 768>>>(x, weight, ker_idx, row_idx, col_idx, vals);

    cudaLaunchConfig_t cfg = {};
    cfg.gridDim  = dim3(PGRID, 1, 1);
    cfg.blockDim = dim3(384, 1, 1);
    cudaLaunchAttribute attr[1];
    attr[0].id = cudaLaunchAttributeProgrammaticStreamSerialization;
    attr[0].val.programmaticStreamSerializationAllowed = 1;
    cfg.attrs = attr;
    cfg.numAttrs = 1;
    cudaLaunchKernelEx(&cfg, k_main, bias, out);
}